// round 5
// baseline (speedup 1.0000x reference)
#include <cuda_runtime.h>
#include <math.h>

#define NN 100000
#define NE 3200000
#define DF 128
#define HID 16
#define NC 2
#define NBLK 391            // ceil(NN/256)
#define GN 64               // nodes per gemm1 block

// ---------------- scratch (no allocations allowed) ----------------
__device__ float  g_dinv[NN];
__device__ float4 g_h1s[NN * 4];   // (x@W1) * dinv
__device__ float4 g_acc1[NN * 4];  // layer-1 aggregate
__device__ float2 g_h2s[NN];       // (relu@W2) * dinv
__device__ int    g_cnt[NN];       // in-edge count (no self loop)
__device__ int    g_scan[NN];      // block-wise inclusive scan
__device__ int    g_off[NN];       // CSR row start
__device__ int    g_cur[NN];       // placement cursor
__device__ int    g_bsum[NBLK];    // per-block totals
__device__ int    g_bsumx[NBLK];   // exclusive scan of block totals
__device__ int    g_eidx[NE];      // CSR: src node per incoming edge

// ---------------- CSR build ----------------

__global__ void k_zero() {
    int i = blockIdx.x * blockDim.x + threadIdx.x;
    if (i < NN) g_cnt[i] = 0;
}

__global__ void k_deg(const int* __restrict__ dst) {
    int e = blockIdx.x * blockDim.x + threadIdx.x;
    if (e < NE) atomicAdd(&g_cnt[dst[e]], 1);  // RED int
}

__global__ void k_dinv() {
    int i = blockIdx.x * blockDim.x + threadIdx.x;
    if (i < NN) g_dinv[i] = rsqrtf((float)g_cnt[i] + 1.0f);  // + self loop
}

// Per-256-block inclusive scan of g_cnt.
__global__ void k_scan_block() {
    __shared__ int sh[256];
    int tid = threadIdx.x;
    int i = blockIdx.x * 256 + tid;
    int v = (i < NN) ? g_cnt[i] : 0;
    sh[tid] = v;
    __syncthreads();
#pragma unroll
    for (int o = 1; o < 256; o <<= 1) {
        int t = (tid >= o) ? sh[tid - o] : 0;
        __syncthreads();
        sh[tid] += t;
        __syncthreads();
    }
    if (i < NN) g_scan[i] = sh[tid];
    if (tid == 255) g_bsum[blockIdx.x] = sh[255];
}

// Scan the 391 block sums (single block of 512).
__global__ void k_scan_tops() {
    __shared__ int sh[512];
    int tid = threadIdx.x;
    int v = (tid < NBLK) ? g_bsum[tid] : 0;
    sh[tid] = v;
    __syncthreads();
#pragma unroll
    for (int o = 1; o < 512; o <<= 1) {
        int t = (tid >= o) ? sh[tid - o] : 0;
        __syncthreads();
        sh[tid] += t;
        __syncthreads();
    }
    if (tid < NBLK) g_bsumx[tid] = sh[tid] - v;  // exclusive
}

__global__ void k_apply() {
    int i = blockIdx.x * blockDim.x + threadIdx.x;
    if (i < NN) {
        int off = g_scan[i] - g_cnt[i] + g_bsumx[i >> 8];  // exclusive start
        g_off[i] = off;
        g_cur[i] = off;
    }
}

__global__ void k_place(const int* __restrict__ src, const int* __restrict__ dst) {
    int e = blockIdx.x * blockDim.x + threadIdx.x;
    if (e < NE) {
        int pos = atomicAdd(&g_cur[dst[e]], 1);
        g_eidx[pos] = src[e];
    }
}

// ---------------- GEMM1 (smem-staged, coalesced) ----------------
// h1s[i] = (x[i] @ W1) * dinv[i]
__global__ void k_gemm1(const float* __restrict__ x, const float* __restrict__ W1) {
    __shared__ __align__(16) float W1s[DF * HID];   // 8 KB
    __shared__ __align__(16) float XS[GN * 132];    // padded rows: conflict-free
    int tid = threadIdx.x;
    int base = blockIdx.x * GN;
    int nb = NN - base; if (nb > GN) nb = GN;

    for (int i = tid; i < DF * HID; i += 256) W1s[i] = W1[i];
    const float4* xg = (const float4*)(x + (size_t)base * DF);
    for (int f = tid; f < nb * 32; f += 256) {     // fully coalesced LDG.128
        int r = f >> 5, k = f & 31;
        *(float4*)&XS[r * 132 + k * 4] = xg[f];
    }
    __syncthreads();

    int n = tid >> 2, c = tid & 3;
    if (n >= nb) return;
    int node = base + n;
    float4 acc = make_float4(0.f, 0.f, 0.f, 0.f);
    const float* xr = &XS[n * 132];
#pragma unroll 4
    for (int k4 = 0; k4 < 32; k4++) {
        float4 xv = *(const float4*)&xr[k4 * 4];
#pragma unroll
        for (int j = 0; j < 4; j++) {
            float xs = (j == 0) ? xv.x : (j == 1) ? xv.y : (j == 2) ? xv.z : xv.w;
            float4 wq = *(const float4*)&W1s[(k4 * 4 + j) * HID + c * 4];
            acc.x = fmaf(xs, wq.x, acc.x);
            acc.y = fmaf(xs, wq.y, acc.y);
            acc.z = fmaf(xs, wq.z, acc.z);
            acc.w = fmaf(xs, wq.w, acc.w);
        }
    }
    float di = g_dinv[node];
    acc.x *= di; acc.y *= di; acc.z *= di; acc.w *= di;
    g_h1s[node * 4 + c] = acc;
}

// ---------------- layer-1 gather (no atomics) ----------------
// acc1[n] = h1s[n] (self loop) + sum over in-edges of h1s[src]
__global__ void k_gather1() {
    int t = blockIdx.x * blockDim.x + threadIdx.x;
    if (t >= NN * 4) return;
    int n = t >> 2, c = t & 3;
    int start = g_off[n];
    int cnt = g_cnt[n];
    const int* ep = &g_eidx[start];
    float4 acc = g_h1s[n * 4 + c];  // self-loop term
    int e = 0;
    for (; e + 4 <= cnt; e += 4) {
        int s0 = ep[e], s1 = ep[e + 1], s2 = ep[e + 2], s3 = ep[e + 3];
        float4 v0 = g_h1s[s0 * 4 + c];
        float4 v1 = g_h1s[s1 * 4 + c];
        float4 v2 = g_h1s[s2 * 4 + c];
        float4 v3 = g_h1s[s3 * 4 + c];
        acc.x += v0.x + v1.x + v2.x + v3.x;
        acc.y += v0.y + v1.y + v2.y + v3.y;
        acc.z += v0.z + v1.z + v2.z + v3.z;
        acc.w += v0.w + v1.w + v2.w + v3.w;
    }
    for (; e < cnt; e++) {
        float4 v = g_h1s[ep[e] * 4 + c];
        acc.x += v.x; acc.y += v.y; acc.z += v.z; acc.w += v.w;
    }
    g_acc1[n * 4 + c] = acc;
}

// Per node: finish layer1 (scale + bias + relu), apply W2, pre-scale for layer2.
__global__ void k_finish1(const float* __restrict__ b1, const float* __restrict__ W2) {
    int i = blockIdx.x * blockDim.x + threadIdx.x;
    if (i >= NN) return;
    float di = g_dinv[i];
    float z0 = 0.0f, z1 = 0.0f;
#pragma unroll
    for (int q = 0; q < 4; q++) {
        float4 a = g_acc1[i * 4 + q];
        float av[4] = {a.x, a.y, a.z, a.w};
#pragma unroll
        for (int j = 0; j < 4; j++) {
            int f = q * 4 + j;
            float v = fmaxf(fmaf(di, av[j], __ldg(&b1[f])), 0.0f);
            z0 = fmaf(v, __ldg(&W2[f * NC + 0]), z0);
            z1 = fmaf(v, __ldg(&W2[f * NC + 1]), z1);
        }
    }
    float2 h;
    h.x = z0 * di;
    h.y = z1 * di;
    g_h2s[i] = h;
}

// ---------------- layer-2 gather + log_softmax (fused) ----------------
__global__ void k_gather2(const float* __restrict__ b2, float* __restrict__ out) {
    int n = blockIdx.x * blockDim.x + threadIdx.x;
    if (n >= NN) return;
    int start = g_off[n];
    int cnt = g_cnt[n];
    const int* ep = &g_eidx[start];
    float2 acc = g_h2s[n];  // self-loop term
    int e = 0;
    for (; e + 4 <= cnt; e += 4) {
        int s0 = ep[e], s1 = ep[e + 1], s2 = ep[e + 2], s3 = ep[e + 3];
        float2 v0 = g_h2s[s0];
        float2 v1 = g_h2s[s1];
        float2 v2 = g_h2s[s2];
        float2 v3 = g_h2s[s3];
        acc.x += v0.x + v1.x + v2.x + v3.x;
        acc.y += v0.y + v1.y + v2.y + v3.y;
    }
    for (; e < cnt; e++) {
        float2 v = g_h2s[ep[e]];
        acc.x += v.x; acc.y += v.y;
    }
    float di = g_dinv[n];
    float z0 = fmaf(di, acc.x, __ldg(&b2[0]));
    float z1 = fmaf(di, acc.y, __ldg(&b2[1]));
    float m = fmaxf(z0, z1);
    float lse = m + logf(expf(z0 - m) + expf(z1 - m));
    float2 o;
    o.x = z0 - lse;
    o.y = z1 - lse;
    ((float2*)out)[n] = o;
}

// ---------------- launch ----------------

extern "C" void kernel_launch(void* const* d_in, const int* in_sizes, int n_in,
                              void* d_out, int out_size) {
    const float* x = 0; const float* W1 = 0; const float* b1 = 0;
    const float* W2 = 0; const float* b2 = 0; const int* ei = 0;
    for (int i = 0; i < n_in; i++) {
        long long s = in_sizes[i];
        if (s == (long long)NN * DF)      x  = (const float*)d_in[i];
        else if (s == DF * HID)           W1 = (const float*)d_in[i];
        else if (s == HID)                b1 = (const float*)d_in[i];
        else if (s == HID * NC)           W2 = (const float*)d_in[i];
        else if (s == NC)                 b2 = (const float*)d_in[i];
        else if (s == 2LL * NE)           ei = (const int*)d_in[i];
    }
    const int* src = ei;        // row 0
    const int* dst = ei + NE;   // row 1

    const int T = 256;
    const int NBn = (NN + T - 1) / T;   // = NBLK
    const int NBe = (NE + T - 1) / T;

    k_zero<<<NBn, T>>>();
    k_deg<<<NBe, T>>>(dst);
    k_dinv<<<NBn, T>>>();
    k_scan_block<<<NBLK, 256>>>();
    k_scan_tops<<<1, 512>>>();
    k_apply<<<NBn, T>>>();
    k_place<<<NBe, T>>>(src, dst);
    k_gemm1<<<(NN + GN - 1) / GN, 256>>>(x, W1);
    k_gather1<<<(NN * 4 + T - 1) / T, T>>>();
    k_finish1<<<NBn, T>>>(b1, W2);
    k_gather2<<<NBn, T>>>(b2, (float*)d_out);
}